// round 14
// baseline (speedup 1.0000x reference)
#include <cuda_runtime.h>
#include <cuda_fp16.h>
#include <math.h>
#include <stdint.h>

// Problem constants
#define BB 256
#define NN 50
#define FF 6144
#define HH 4
#define OO 64
#define NT (HH*OO)          // 256
#define MT (BB*NN)          // 12800

// GEMM tiling (R12 config): CTA tile 128x256, BK=64, 512 thr, warp 32x64
#define BM 128
#define BN 256
#define BK 64
#define RSAH 72
#define RSB 72
#define NSTG 3
#define A_ST_BYTES (BM * RSAH * 2)      // 18432
#define B_ST_BYTES (BN * RSB  * 2)      // 36864
#define SMEM_BYTES (NSTG * (A_ST_BYTES + B_ST_BYTES))   // 165888
#define KUNITS (FF/BK)                  // 96
#define HALF_TILES 50
#define HALF_UNITS (HALF_TILES * KUNITS)   // 4800
#define GRID_G 148
#define NTHREADS 512

__device__ float  g_Wh[(size_t)MT * NT];
__device__ __half g_Bth[(size_t)NT * FF];
__device__ unsigned char g_adj[(size_t)BB * NN * NN];

__device__ __forceinline__ uint32_t smem_u32(const void* p) {
    uint32_t a;
    asm("{ .reg .u64 t; cvta.to.shared.u64 t, %1; cvt.u32.u64 %0, t; }" : "=r"(a) : "l"(p));
    return a;
}
__device__ __forceinline__ unsigned packh2(float x, float y) {
    half2 h = __floats2half2_rn(x, y);
    return *(unsigned*)&h;
}
__device__ __forceinline__ void mma_f16(float c[4],
                                        const unsigned a[4],
                                        unsigned b0, unsigned b1) {
    asm volatile(
        "mma.sync.aligned.m16n8k16.row.col.f32.f16.f16.f32 "
        "{%0,%1,%2,%3}, {%4,%5,%6,%7}, {%8,%9}, {%0,%1,%2,%3};"
        : "+f"(c[0]), "+f"(c[1]), "+f"(c[2]), "+f"(c[3])
        : "r"(a[0]), "r"(a[1]), "r"(a[2]), "r"(a[3]),
          "r"(b0), "r"(b1));
}
#define CP16(dst, src) \
    asm volatile("cp.async.cg.shared.global [%0], [%1], 16;" :: "r"(dst), "l"(src))
#define CP_COMMIT() asm volatile("cp.async.commit_group;" ::: "memory")
#define CP_WAIT1()  asm volatile("cp.async.wait_group 1;"  ::: "memory")
#define LDSM_X4(r0, r1, r2, r3, ad)                                           \
    asm volatile("ldmatrix.sync.aligned.m8n8.x4.shared.b16 {%0,%1,%2,%3}, [%4];" \
        : "=r"(r0), "=r"(r1), "=r"(r2), "=r"(r3) : "r"(ad))

// ---------------------------------------------------------------------------
__global__ void zero_kernel()
{
    size_t i = (size_t)blockIdx.x * blockDim.x + threadIdx.x;
    float4* p = (float4*)g_Wh;
    size_t n4 = (size_t)MT * NT / 4;
    for (; i < n4; i += (size_t)gridDim.x * blockDim.x)
        p[i] = make_float4(0.f, 0.f, 0.f, 0.f);
}

// ---------------------------------------------------------------------------
__global__ __launch_bounds__(256)
void adj_kernel(const float* __restrict__ probs, const float* __restrict__ u)
{
    int idx = blockIdx.x * 256 + threadIdx.x;
    if (idx >= BB * NN * NN) return;
    float p = probs[idx];
    float2 uv = *(const float2*)&u[(size_t)idx * 2];
    float x0 = p, x1 = 1.f - p;
    float mx = fmaxf(x0, x1);
    float e0 = __expf(x0 - mx), e1 = __expf(x1 - mx);
    float inv = 1.f / (e0 + e1);
    float l0 = __logf(e0 * inv + 1e-5f);
    float l1 = __logf(e1 * inv + 1e-5f);
    float g0 = -__logf(-__logf(uv.x + 1e-10f) + 1e-10f);
    float g1 = -__logf(-__logf(uv.y + 1e-10f) + 1e-10f);
    g_adj[idx] = (l0 + g0 >= l1 + g1) ? 1 : 0;
}

// ---------------------------------------------------------------------------
__global__ __launch_bounds__(256)
void wT_kernel(const float* __restrict__ W)
{
    __shared__ float t[32][65];
    const int f0 = blockIdx.x * 32;
    const int h  = blockIdx.y;
    for (int i = threadIdx.x; i < 32 * 64; i += 256) {
        int fi = i >> 6, o = i & 63;
        t[fi][o] = W[((size_t)h * FF + f0 + fi) * OO + o];
    }
    __syncthreads();
    for (int i = threadIdx.x; i < 32 * 64; i += 256) {
        int o = i >> 5, fi = i & 31;
        g_Bth[(size_t)(h * 64 + o) * FF + f0 + fi] = __float2half_rn(t[fi][o]);
    }
}

// ---------------------------------------------------------------------------
// Kernel A (R12): persistent fp16 GEMM over tile range [tile0, tile0+50).
// ---------------------------------------------------------------------------
__global__ __launch_bounds__(NTHREADS, 1)
void gemm_f16(const float* __restrict__ hmat, int tile0)
{
    extern __shared__ char smraw[];
    __half* Ash = (__half*)smraw;
    __half* Bsh = (__half*)(smraw + NSTG * A_ST_BYTES);
    const uint32_t aB = smem_u32(Ash);
    const uint32_t bB = smem_u32(Bsh);

    const int tid  = threadIdx.x;
    const int lane = tid & 31;
    const int wid  = tid >> 5;
    const int wm   = wid & 3;              // 4 x 32 m
    const int wn   = wid >> 2;             // 4 x 64 n

    const int c  = blockIdx.x;
    const int ubase = tile0 * KUNITS;
    int u        = ubase + (int)(((long long)HALF_UNITS * c) / GRID_G);
    const int u1 = ubase + (int)(((long long)HALF_UNITS * (c + 1)) / GRID_G);

    float4 va[4];

#define LDG_A(Abase, kt)                                                      \
    {                                                                         \
        const int k0 = (kt) * BK;                                             \
        _Pragma("unroll")                                                     \
        for (int i = 0; i < 4; i++) {                                         \
            int p = tid + i * NTHREADS;                                       \
            int m = p >> 4, kq = (p & 15) * 4;                                \
            va[i] = *(const float4*)((Abase) + (size_t)m * FF + k0 + kq);     \
        }                                                                     \
    }
#define STS_A(slot)                                                           \
    {                                                                         \
        _Pragma("unroll")                                                     \
        for (int i = 0; i < 4; i++) {                                         \
            int p = tid + i * NTHREADS;                                       \
            int m = p >> 4, kq = (p & 15) * 4;                                \
            uint2 v = make_uint2(packh2(va[i].x, va[i].y),                    \
                                 packh2(va[i].z, va[i].w));                   \
            *(uint2*)(Ash + (slot) * (BM * RSAH) + m * RSAH + kq) = v;        \
        }                                                                     \
    }
#define ISSUE_B(kt, slot)                                                     \
    {                                                                         \
        const int k0 = (kt) * BK;                                             \
        _Pragma("unroll")                                                     \
        for (int i = 0; i < 4; i++) {                                         \
            int p = tid + i * NTHREADS;                                       \
            int n = p >> 3, k8 = (p & 7) * 8;                                 \
            CP16(bB + (slot) * B_ST_BYTES + (n * RSB + k8) * 2,               \
                 g_Bth + (size_t)n * FF + k0 + k8);                           \
        }                                                                     \
    }

    while (u < u1) {
        const int tile = u / KUNITS;
        const int kbeg = u - tile * KUNITS;
        const int seg  = min(KUNITS - kbeg, u1 - u);
        const int kend = kbeg + seg;
        const int row0 = tile * BM;
        const float* Abase = hmat + (size_t)row0 * FF;

#pragma unroll
        for (int s = 0; s < 2; s++) {
            if (s < seg) ISSUE_B(kbeg + s, s);
            CP_COMMIT();
        }
        LDG_A(Abase, kbeg);
        STS_A(0);
        if (kbeg + 1 < kend) LDG_A(Abase, kbeg + 1);

        float acc[2][8][4];
#pragma unroll
        for (int i = 0; i < 2; i++)
#pragma unroll
            for (int j = 0; j < 8; j++)
#pragma unroll
                for (int q = 0; q < 4; q++) acc[i][j][q] = 0.f;

        int slot = 0;
        for (int kt = kbeg; kt < kend; kt++) {
            CP_WAIT1();
            __syncthreads();
            {
                int s2 = slot + 2; if (s2 >= NSTG) s2 -= NSTG;
                if (kt + 2 < kend) ISSUE_B(kt + 2, s2);
                CP_COMMIT();
            }
            if (kt + 1 < kend) {
                int s1 = slot + 1; if (s1 >= NSTG) s1 -= NSTG;
                STS_A(s1);
            }
            if (kt + 2 < kend) LDG_A(Abase, kt + 2);

            const uint32_t aS = aB + slot * A_ST_BYTES;
            const uint32_t bS = bB + slot * B_ST_BYTES;
            const int rlo = lane & 15;
            const int chi = (lane >> 4) * 8;
            const int j8  = lane & 7;
            const int mi  = lane >> 3;
            const uint32_t bRow = bS +
                ((wn * 64 + (mi >> 1) * 8 + j8) * RSB + (mi & 1) * 8) * 2;

#pragma unroll
            for (int ks = 0; ks < 4; ks++) {
                const int kboff = ks * 16 * 2;

                unsigned af[2][4];
#pragma unroll
                for (int mt = 0; mt < 2; mt++) {
                    const int mrow = wm * 32 + mt * 16;
                    uint32_t ad = aS + ((mrow + rlo) * RSAH + ks * 16 + chi) * 2;
                    LDSM_X4(af[mt][0], af[mt][1], af[mt][2], af[mt][3], ad);
                }

                unsigned bfr[2][4];
                LDSM_X4(bfr[0][0], bfr[0][1], bfr[0][2], bfr[0][3],
                        bRow + kboff);
#pragma unroll
                for (int pr = 0; pr < 4; pr++) {
                    const int cb = pr & 1;
                    if (pr < 3) {
                        LDSM_X4(bfr[cb ^ 1][0], bfr[cb ^ 1][1],
                                bfr[cb ^ 1][2], bfr[cb ^ 1][3],
                                bRow + kboff + (pr + 1) * 16 * RSB * 2);
                    }
#pragma unroll
                    for (int mt = 0; mt < 2; mt++) {
                        mma_f16(acc[mt][2 * pr],     af[mt], bfr[cb][0], bfr[cb][1]);
                        mma_f16(acc[mt][2 * pr + 1], af[mt], bfr[cb][2], bfr[cb][3]);
                    }
                }
            }
            if (++slot == NSTG) slot = 0;
        }
        __syncthreads();

#pragma unroll
        for (int mt = 0; mt < 2; mt++) {
            int r = row0 + wm * 32 + mt * 16 + (lane >> 2);
#pragma unroll
            for (int nt = 0; nt < 8; nt++) {
                int cc = wn * 64 + nt * 8 + (lane & 3) * 2;
                atomicAdd(&g_Wh[(size_t)r * NT + cc],           acc[mt][nt][0]);
                atomicAdd(&g_Wh[(size_t)r * NT + cc + 1],       acc[mt][nt][1]);
                atomicAdd(&g_Wh[(size_t)(r + 8) * NT + cc],     acc[mt][nt][2]);
                atomicAdd(&g_Wh[(size_t)(r + 8) * NT + cc + 1], acc[mt][nt][3]);
            }
        }

        u += seg;
    }
#undef LDG_A
#undef STS_A
#undef ISSUE_B
}

// ---------------------------------------------------------------------------
// Kernel B: GAT attention + ELU for b in [b0, b0+gridDim.x).
// ---------------------------------------------------------------------------
#define NP 52
__global__ __launch_bounds__(256, 5)
void attn_kernel(const float* __restrict__ a, float* __restrict__ out, int b0)
{
    __shared__ float sWh[NP][68];
    __shared__ float sA2[NP][68];
    __shared__ float sE[NP][NP];
    __shared__ float sS1[NN];
    __shared__ unsigned char sAdj[NN * NN];

    const int b    = b0 + blockIdx.x;
    const int h    = blockIdx.y;
    const int tid  = threadIdx.x;
    const int lane = tid & 31;
    const int wid  = tid >> 5;

    {
        const unsigned* src = (const unsigned*)(g_adj + (size_t)b * NN * NN);
        unsigned* dst = (unsigned*)sAdj;
        for (int i = tid; i < NN * NN / 4; i += 256) dst[i] = src[i];
    }

    if (tid < 2 * 68) {
        int r = 50 + tid / 68, cidx = tid % 68;
        sWh[r][cidx] = 0.f;
        sA2[r][cidx] = 0.f;
    }

    for (int idx = tid; idx < NN * OO / 4; idx += 256) {
        int n_ = idx >> 4;
        int o4 = (idx & 15) * 4;
        float4 w  = *(const float4*)&g_Wh[(size_t)(b * NN + n_) * NT + h * OO + o4];
        float4 av = *(const float4*)&a[(size_t)(h * NN + n_) * (2 * OO) + OO + o4];
        *(float4*)&sWh[n_][o4] = w;
        *(float4*)&sA2[n_][o4] = av;
    }
    __syncthreads();

    for (int n_ = wid; n_ < NN; n_ += 8) {
        float a1v0 = a[(size_t)(h * NN + n_) * (2 * OO) + lane];
        float a1v1 = a[(size_t)(h * NN + n_) * (2 * OO) + lane + 32];
        float v = sWh[n_][lane] * a1v0 + sWh[n_][lane + 32] * a1v1;
#pragma unroll
        for (int off = 16; off; off >>= 1) v += __shfl_xor_sync(0xffffffffu, v, off);
        if (lane == 0) sS1[n_] = v;
    }

    if (tid < 169) {
        const int n0 = (tid / 13) * 4;
        const int m0 = (tid % 13) * 4;
        float acc[4][4];
#pragma unroll
        for (int i = 0; i < 4; i++)
#pragma unroll
            for (int j = 0; j < 4; j++) acc[i][j] = 0.f;
#pragma unroll 8
        for (int o = 0; o < OO; o++) {
            float av[4], wv[4];
#pragma unroll
            for (int i = 0; i < 4; i++) av[i] = sA2[n0 + i][o];
#pragma unroll
            for (int j = 0; j < 4; j++) wv[j] = sWh[m0 + j][o];
#pragma unroll
            for (int i = 0; i < 4; i++)
#pragma unroll
                for (int j = 0; j < 4; j++)
                    acc[i][j] = fmaf(av[i], wv[j], acc[i][j]);
        }
#pragma unroll
        for (int i = 0; i < 4; i++)
#pragma unroll
            for (int j = 0; j < 4; j++) sE[n0 + i][m0 + j] = acc[i][j];
    }
    __syncthreads();

    for (int n_ = wid; n_ < NN; n_ += 8) {
        float s1v = sS1[n_];
        int m0 = lane, m1 = lane + 32;
        float t0 = s1v + sE[n_][m0];
        t0 = (t0 >= 0.f) ? t0 : 0.2f * t0;
        float v0 = sAdj[n_ * NN + m0] ? t0 : -9e15f;
        float v1 = -9e15f;
        if (m1 < NN) {
            float t1 = s1v + sE[n_][m1];
            t1 = (t1 >= 0.f) ? t1 : 0.2f * t1;
            v1 = sAdj[n_ * NN + m1] ? t1 : -9e15f;
        }
        float mx = fmaxf(v0, v1);
#pragma unroll
        for (int off = 16; off; off >>= 1)
            mx = fmaxf(mx, __shfl_xor_sync(0xffffffffu, mx, off));
        float e0_ = __expf(v0 - mx);
        float e1_ = (m1 < NN) ? __expf(v1 - mx) : 0.f;
        float sum = e0_ + e1_;
#pragma unroll
        for (int off = 16; off; off >>= 1)
            sum += __shfl_xor_sync(0xffffffffu, sum, off);
        float inv = 1.f / sum;
        sE[n_][m0] = e0_ * inv;
        if (m1 < NN) sE[n_][m1] = e1_ * inv;
    }
    __syncthreads();

    if (tid < 208) {
        const int n0 = (tid / 16) * 4;
        const int o4 = (tid % 16) * 4;
        float4 acc[4];
#pragma unroll
        for (int i = 0; i < 4; i++) acc[i] = make_float4(0.f, 0.f, 0.f, 0.f);
#pragma unroll 5
        for (int m = 0; m < NN; m++) {
            float4 wv = *(const float4*)&sWh[m][o4];
#pragma unroll
            for (int i = 0; i < 4; i++) {
                float at = sE[n0 + i][m];
                acc[i].x = fmaf(at, wv.x, acc[i].x);
                acc[i].y = fmaf(at, wv.y, acc[i].y);
                acc[i].z = fmaf(at, wv.z, acc[i].z);
                acc[i].w = fmaf(at, wv.w, acc[i].w);
            }
        }
#pragma unroll
        for (int i = 0; i < 4; i++) {
            int n_ = n0 + i;
            if (n_ < NN) {
                float4 wv = *(const float4*)&sWh[n_][o4];
                float4 v = make_float4(acc[i].x + 0.3f * wv.x,
                                       acc[i].y + 0.3f * wv.y,
                                       acc[i].z + 0.3f * wv.z,
                                       acc[i].w + 0.3f * wv.w);
                v.x = (v.x > 0.f) ? v.x : (__expf(v.x) - 1.f);
                v.y = (v.y > 0.f) ? v.y : (__expf(v.y) - 1.f);
                v.z = (v.z > 0.f) ? v.z : (__expf(v.z) - 1.f);
                v.w = (v.w > 0.f) ? v.w : (__expf(v.w) - 1.f);
                *(float4*)&out[(size_t)(b * NN + n_) * NT + h * OO + o4] = v;
            }
        }
    }
}

// ---------------------------------------------------------------------------
extern "C" void kernel_launch(void* const* d_in, const int* in_sizes, int n_in,
                              void* d_out, int out_size)
{
    const float* h_    = (const float*)d_in[0];  // (B, N, F)
    const float* probs = (const float*)d_in[1];  // (B, N*N)
    const float* u_    = (const float*)d_in[2];  // (B, N*N, 2)
    const float* W_    = (const float*)d_in[3];  // (H, F, O)
    const float* a_    = (const float*)d_in[4];  // (H, N, 2*O)
    float* out = (float*)d_out;

    // one-time resource init (streams/events are infra, not work state)
    static cudaStream_t sideStream = nullptr;
    static cudaEvent_t evFork = nullptr, evJoin = nullptr;
    if (sideStream == nullptr) {
        cudaStreamCreateWithFlags(&sideStream, cudaStreamNonBlocking);
        cudaEventCreateWithFlags(&evFork, cudaEventDisableTiming);
        cudaEventCreateWithFlags(&evJoin, cudaEventDisableTiming);
    }

    cudaFuncSetAttribute(gemm_f16, cudaFuncAttributeMaxDynamicSharedMemorySize,
                         SMEM_BYTES);

    // main stream: prep + first half of GEMM (tiles 0..49 -> b in [0,128))
    zero_kernel<<<592, 256>>>();
    adj_kernel<<<(BB * NN * NN + 255) / 256, 256>>>(probs, u_);
    dim3 tgrid(FF / 32, HH);
    wT_kernel<<<tgrid, 256>>>(W_);
    gemm_f16<<<GRID_G, NTHREADS, SMEM_BYTES>>>(h_, 0);

    // fork: attn on first half runs concurrently with second-half GEMM
    cudaEventRecord(evFork, 0);
    cudaStreamWaitEvent(sideStream, evFork, 0);
    {
        dim3 agrid(BB / 2, HH);
        attn_kernel<<<agrid, 256, 0, sideStream>>>(a_, out, 0);
    }

    // main stream: second half of GEMM (tiles 50..99 -> b in [128,256))
    gemm_f16<<<GRID_G, NTHREADS, SMEM_BYTES>>>(h_, HALF_TILES);

    // join, then attn on second half
    cudaEventRecord(evJoin, sideStream);
    cudaStreamWaitEvent(0, evJoin, 0);
    {
        dim3 agrid(BB / 2, HH);
        attn_kernel<<<agrid, 256>>>(a_, out, BB / 2);
    }
}

// round 15
// speedup vs baseline: 1.1954x; 1.1954x over previous
#include <cuda_runtime.h>
#include <cuda_fp16.h>
#include <math.h>
#include <stdint.h>

// Problem constants
#define BB 256
#define NN 50
#define FF 6144
#define HH 4
#define OO 64
#define NT (HH*OO)          // 256
#define MT (BB*NN)          // 12800

// GEMM tiling (R12): CTA tile 128x256, BK=64, 512 thr, warp 32x64
#define BM 128
#define BN 256
#define BK 64
#define RSAH 72
#define RSB 72
#define NSTG 3
#define A_ST_BYTES (BM * RSAH * 2)      // 18432
#define B_ST_BYTES (BN * RSB  * 2)      // 36864
#define SMEM_BYTES (NSTG * (A_ST_BYTES + B_ST_BYTES))   // 165888
#define NTILES (MT/BM)                  // 100
#define KUNITS (FF/BK)                  // 96
#define UNITS_TOTAL (NTILES * KUNITS)   // 9600
#define GRID_G 148
#define NTHREADS 512

// fused prep kernel block ranges
#define ZERO_BLKS 592
#define ADJ_BLKS  ((BB * NN * NN + 255) / 256)   // 2500
#define WT_BLKS   ((FF / 32) * HH)               // 768
#define PREP_BLKS (ZERO_BLKS + ADJ_BLKS + WT_BLKS)

__device__ float  g_Wh[(size_t)MT * NT];
__device__ __half g_Bth[(size_t)NT * FF];
__device__ unsigned char g_adj[(size_t)BB * NN * NN];

__device__ __forceinline__ uint32_t smem_u32(const void* p) {
    uint32_t a;
    asm("{ .reg .u64 t; cvta.to.shared.u64 t, %1; cvt.u32.u64 %0, t; }" : "=r"(a) : "l"(p));
    return a;
}
__device__ __forceinline__ unsigned packh2(float x, float y) {
    half2 h = __floats2half2_rn(x, y);
    return *(unsigned*)&h;
}
__device__ __forceinline__ void mma_f16(float c[4],
                                        const unsigned a[4],
                                        unsigned b0, unsigned b1) {
    asm volatile(
        "mma.sync.aligned.m16n8k16.row.col.f32.f16.f16.f32 "
        "{%0,%1,%2,%3}, {%4,%5,%6,%7}, {%8,%9}, {%0,%1,%2,%3};"
        : "+f"(c[0]), "+f"(c[1]), "+f"(c[2]), "+f"(c[3])
        : "r"(a[0]), "r"(a[1]), "r"(a[2]), "r"(a[3]),
          "r"(b0), "r"(b1));
}
#define CP16(dst, src) \
    asm volatile("cp.async.cg.shared.global [%0], [%1], 16;" :: "r"(dst), "l"(src))
#define CP_COMMIT() asm volatile("cp.async.commit_group;" ::: "memory")
#define CP_WAIT1()  asm volatile("cp.async.wait_group 1;"  ::: "memory")
#define LDSM_X4(r0, r1, r2, r3, ad)                                           \
    asm volatile("ldmatrix.sync.aligned.m8n8.x4.shared.b16 {%0,%1,%2,%3}, [%4];" \
        : "=r"(r0), "=r"(r1), "=r"(r2), "=r"(r3) : "r"(ad))

// ---------------------------------------------------------------------------
// Fused prep: zero g_Wh | Gumbel adjacency | W transpose+fp16 — one launch.
// ---------------------------------------------------------------------------
__global__ __launch_bounds__(256)
void prep_kernel(const float* __restrict__ probs, const float* __restrict__ u,
                 const float* __restrict__ W)
{
    const int blk = blockIdx.x;
    const int tid = threadIdx.x;

    if (blk < ZERO_BLKS) {
        // zero g_Wh (grid-stride over 592 blocks)
        size_t i = (size_t)blk * 256 + tid;
        float4* p = (float4*)g_Wh;
        size_t n4 = (size_t)MT * NT / 4;
        for (; i < n4; i += (size_t)ZERO_BLKS * 256)
            p[i] = make_float4(0.f, 0.f, 0.f, 0.f);
    } else if (blk < ZERO_BLKS + ADJ_BLKS) {
        int idx = (blk - ZERO_BLKS) * 256 + tid;
        if (idx < BB * NN * NN) {
            float p = probs[idx];
            float2 uv = *(const float2*)&u[(size_t)idx * 2];
            float x0 = p, x1 = 1.f - p;
            float mx = fmaxf(x0, x1);
            float e0 = __expf(x0 - mx), e1 = __expf(x1 - mx);
            float inv = 1.f / (e0 + e1);
            float l0 = __logf(e0 * inv + 1e-5f);
            float l1 = __logf(e1 * inv + 1e-5f);
            float g0 = -__logf(-__logf(uv.x + 1e-10f) + 1e-10f);
            float g1 = -__logf(-__logf(uv.y + 1e-10f) + 1e-10f);
            g_adj[idx] = (l0 + g0 >= l1 + g1) ? 1 : 0;
        }
    } else {
        // W transpose: block handles a 32(f) x 64(o) tile of one head
        __shared__ float t[32][65];
        int wblk = blk - ZERO_BLKS - ADJ_BLKS;        // 0..767
        const int f0 = (wblk % (FF / 32)) * 32;
        const int h  = wblk / (FF / 32);
        for (int i = tid; i < 32 * 64; i += 256) {
            int fi = i >> 6, o = i & 63;
            t[fi][o] = W[((size_t)h * FF + f0 + fi) * OO + o];
        }
        __syncthreads();
        for (int i = tid; i < 32 * 64; i += 256) {
            int o = i >> 5, fi = i & 31;
            g_Bth[(size_t)(h * 64 + o) * FF + f0 + fi] = __float2half_rn(t[fi][o]);
        }
    }
}

// ---------------------------------------------------------------------------
// Kernel A (R12): persistent fp16 GEMM, BK=64 phases, 16 warps, 32x64 tiles.
// ---------------------------------------------------------------------------
__global__ __launch_bounds__(NTHREADS, 1)
void gemm_f16(const float* __restrict__ hmat)
{
    extern __shared__ char smraw[];
    __half* Ash = (__half*)smraw;                          // [NSTG][BM][RSAH]
    __half* Bsh = (__half*)(smraw + NSTG * A_ST_BYTES);    // [NSTG][BN][RSB]
    const uint32_t aB = smem_u32(Ash);
    const uint32_t bB = smem_u32(Bsh);

    const int tid  = threadIdx.x;
    const int lane = tid & 31;
    const int wid  = tid >> 5;
    const int wm   = wid & 3;              // 4 x 32 m
    const int wn   = wid >> 2;             // 4 x 64 n

    const int c  = blockIdx.x;
    int u        = (int)(((long long)UNITS_TOTAL * c) / GRID_G);
    const int u1 = (int)(((long long)UNITS_TOTAL * (c + 1)) / GRID_G);

    float4 va[4];

#define LDG_A(Abase, kt)                                                      \
    {                                                                         \
        const int k0 = (kt) * BK;                                             \
        _Pragma("unroll")                                                     \
        for (int i = 0; i < 4; i++) {                                         \
            int p = tid + i * NTHREADS;                                       \
            int m = p >> 4, kq = (p & 15) * 4;                                \
            va[i] = *(const float4*)((Abase) + (size_t)m * FF + k0 + kq);     \
        }                                                                     \
    }
#define STS_A(slot)                                                           \
    {                                                                         \
        _Pragma("unroll")                                                     \
        for (int i = 0; i < 4; i++) {                                         \
            int p = tid + i * NTHREADS;                                       \
            int m = p >> 4, kq = (p & 15) * 4;                                \
            uint2 v = make_uint2(packh2(va[i].x, va[i].y),                    \
                                 packh2(va[i].z, va[i].w));                   \
            *(uint2*)(Ash + (slot) * (BM * RSAH) + m * RSAH + kq) = v;        \
        }                                                                     \
    }
#define ISSUE_B(kt, slot)                                                     \
    {                                                                         \
        const int k0 = (kt) * BK;                                             \
        _Pragma("unroll")                                                     \
        for (int i = 0; i < 4; i++) {                                         \
            int p = tid + i * NTHREADS;                                       \
            int n = p >> 3, k8 = (p & 7) * 8;                                 \
            CP16(bB + (slot) * B_ST_BYTES + (n * RSB + k8) * 2,               \
                 g_Bth + (size_t)n * FF + k0 + k8);                           \
        }                                                                     \
    }

    while (u < u1) {
        const int tile = u / KUNITS;
        const int kbeg = u - tile * KUNITS;
        const int seg  = min(KUNITS - kbeg, u1 - u);
        const int kend = kbeg + seg;
        const int row0 = tile * BM;
        const float* Abase = hmat + (size_t)row0 * FF;

#pragma unroll
        for (int s = 0; s < 2; s++) {
            if (s < seg) ISSUE_B(kbeg + s, s);
            CP_COMMIT();
        }
        LDG_A(Abase, kbeg);
        STS_A(0);
        if (kbeg + 1 < kend) LDG_A(Abase, kbeg + 1);

        float acc[2][8][4];
#pragma unroll
        for (int i = 0; i < 2; i++)
#pragma unroll
            for (int j = 0; j < 8; j++)
#pragma unroll
                for (int q = 0; q < 4; q++) acc[i][j][q] = 0.f;

        int slot = 0;
        for (int kt = kbeg; kt < kend; kt++) {
            CP_WAIT1();
            __syncthreads();
            {
                int s2 = slot + 2; if (s2 >= NSTG) s2 -= NSTG;
                if (kt + 2 < kend) ISSUE_B(kt + 2, s2);
                CP_COMMIT();
            }
            if (kt + 1 < kend) {
                int s1 = slot + 1; if (s1 >= NSTG) s1 -= NSTG;
                STS_A(s1);
            }
            if (kt + 2 < kend) LDG_A(Abase, kt + 2);

            const uint32_t aS = aB + slot * A_ST_BYTES;
            const uint32_t bS = bB + slot * B_ST_BYTES;
            const int rlo = lane & 15;
            const int chi = (lane >> 4) * 8;
            const int j8  = lane & 7;
            const int mi  = lane >> 3;
            const uint32_t bRow = bS +
                ((wn * 64 + (mi >> 1) * 8 + j8) * RSB + (mi & 1) * 8) * 2;

#pragma unroll
            for (int ks = 0; ks < 4; ks++) {
                const int kboff = ks * 16 * 2;

                unsigned af[2][4];
#pragma unroll
                for (int mt = 0; mt < 2; mt++) {
                    const int mrow = wm * 32 + mt * 16;
                    uint32_t ad = aS + ((mrow + rlo) * RSAH + ks * 16 + chi) * 2;
                    LDSM_X4(af[mt][0], af[mt][1], af[mt][2], af[mt][3], ad);
                }

                unsigned bfr[2][4];
                LDSM_X4(bfr[0][0], bfr[0][1], bfr[0][2], bfr[0][3],
                        bRow + kboff);
#pragma unroll
                for (int pr = 0; pr < 4; pr++) {
                    const int cb = pr & 1;
                    if (pr < 3) {
                        LDSM_X4(bfr[cb ^ 1][0], bfr[cb ^ 1][1],
                                bfr[cb ^ 1][2], bfr[cb ^ 1][3],
                                bRow + kboff + (pr + 1) * 16 * RSB * 2);
                    }
#pragma unroll
                    for (int mt = 0; mt < 2; mt++) {
                        mma_f16(acc[mt][2 * pr],     af[mt], bfr[cb][0], bfr[cb][1]);
                        mma_f16(acc[mt][2 * pr + 1], af[mt], bfr[cb][2], bfr[cb][3]);
                    }
                }
            }
            if (++slot == NSTG) slot = 0;
        }
        __syncthreads();

#pragma unroll
        for (int mt = 0; mt < 2; mt++) {
            int r = row0 + wm * 32 + mt * 16 + (lane >> 2);
#pragma unroll
            for (int nt = 0; nt < 8; nt++) {
                int cc = wn * 64 + nt * 8 + (lane & 3) * 2;
                atomicAdd(&g_Wh[(size_t)r * NT + cc],           acc[mt][nt][0]);
                atomicAdd(&g_Wh[(size_t)r * NT + cc + 1],       acc[mt][nt][1]);
                atomicAdd(&g_Wh[(size_t)(r + 8) * NT + cc],     acc[mt][nt][2]);
                atomicAdd(&g_Wh[(size_t)(r + 8) * NT + cc + 1], acc[mt][nt][3]);
            }
        }

        u += seg;
    }
#undef LDG_A
#undef STS_A
#undef ISSUE_B
}

// ---------------------------------------------------------------------------
// Kernel B: GAT attention + ELU. grid (256,4), 256 threads, 5 blocks/SM.
// ---------------------------------------------------------------------------
#define NP 52
__global__ __launch_bounds__(256, 5)
void attn_kernel(const float* __restrict__ a, float* __restrict__ out)
{
    __shared__ float sWh[NP][68];
    __shared__ float sA2[NP][68];
    __shared__ float sE[NP][NP];
    __shared__ float sS1[NN];
    __shared__ unsigned char sAdj[NN * NN];

    const int b    = blockIdx.x;
    const int h    = blockIdx.y;
    const int tid  = threadIdx.x;
    const int lane = tid & 31;
    const int wid  = tid >> 5;

    {
        const unsigned* src = (const unsigned*)(g_adj + (size_t)b * NN * NN);
        unsigned* dst = (unsigned*)sAdj;
        for (int i = tid; i < NN * NN / 4; i += 256) dst[i] = src[i];
    }

    if (tid < 2 * 68) {
        int r = 50 + tid / 68, cidx = tid % 68;
        sWh[r][cidx] = 0.f;
        sA2[r][cidx] = 0.f;
    }

    for (int idx = tid; idx < NN * OO / 4; idx += 256) {
        int n_ = idx >> 4;
        int o4 = (idx & 15) * 4;
        float4 w  = *(const float4*)&g_Wh[(size_t)(b * NN + n_) * NT + h * OO + o4];
        float4 av = *(const float4*)&a[(size_t)(h * NN + n_) * (2 * OO) + OO + o4];
        *(float4*)&sWh[n_][o4] = w;
        *(float4*)&sA2[n_][o4] = av;
    }
    __syncthreads();

    for (int n_ = wid; n_ < NN; n_ += 8) {
        float a1v0 = a[(size_t)(h * NN + n_) * (2 * OO) + lane];
        float a1v1 = a[(size_t)(h * NN + n_) * (2 * OO) + lane + 32];
        float v = sWh[n_][lane] * a1v0 + sWh[n_][lane + 32] * a1v1;
#pragma unroll
        for (int off = 16; off; off >>= 1) v += __shfl_xor_sync(0xffffffffu, v, off);
        if (lane == 0) sS1[n_] = v;
    }

    if (tid < 169) {
        const int n0 = (tid / 13) * 4;
        const int m0 = (tid % 13) * 4;
        float acc[4][4];
#pragma unroll
        for (int i = 0; i < 4; i++)
#pragma unroll
            for (int j = 0; j < 4; j++) acc[i][j] = 0.f;
#pragma unroll 8
        for (int o = 0; o < OO; o++) {
            float av[4], wv[4];
#pragma unroll
            for (int i = 0; i < 4; i++) av[i] = sA2[n0 + i][o];
#pragma unroll
            for (int j = 0; j < 4; j++) wv[j] = sWh[m0 + j][o];
#pragma unroll
            for (int i = 0; i < 4; i++)
#pragma unroll
                for (int j = 0; j < 4; j++)
                    acc[i][j] = fmaf(av[i], wv[j], acc[i][j]);
        }
#pragma unroll
        for (int i = 0; i < 4; i++)
#pragma unroll
            for (int j = 0; j < 4; j++) sE[n0 + i][m0 + j] = acc[i][j];
    }
    __syncthreads();

    for (int n_ = wid; n_ < NN; n_ += 8) {
        float s1v = sS1[n_];
        int m0 = lane, m1 = lane + 32;
        float t0 = s1v + sE[n_][m0];
        t0 = (t0 >= 0.f) ? t0 : 0.2f * t0;
        float v0 = sAdj[n_ * NN + m0] ? t0 : -9e15f;
        float v1 = -9e15f;
        if (m1 < NN) {
            float t1 = s1v + sE[n_][m1];
            t1 = (t1 >= 0.f) ? t1 : 0.2f * t1;
            v1 = sAdj[n_ * NN + m1] ? t1 : -9e15f;
        }
        float mx = fmaxf(v0, v1);
#pragma unroll
        for (int off = 16; off; off >>= 1)
            mx = fmaxf(mx, __shfl_xor_sync(0xffffffffu, mx, off));
        float e0_ = __expf(v0 - mx);
        float e1_ = (m1 < NN) ? __expf(v1 - mx) : 0.f;
        float sum = e0_ + e1_;
#pragma unroll
        for (int off = 16; off; off >>= 1)
            sum += __shfl_xor_sync(0xffffffffu, sum, off);
        float inv = 1.f / sum;
        sE[n_][m0] = e0_ * inv;
        if (m1 < NN) sE[n_][m1] = e1_ * inv;
    }
    __syncthreads();

    if (tid < 208) {
        const int n0 = (tid / 16) * 4;
        const int o4 = (tid % 16) * 4;
        float4 acc[4];
#pragma unroll
        for (int i = 0; i < 4; i++) acc[i] = make_float4(0.f, 0.f, 0.f, 0.f);
#pragma unroll 5
        for (int m = 0; m < NN; m++) {
            float4 wv = *(const float4*)&sWh[m][o4];
#pragma unroll
            for (int i = 0; i < 4; i++) {
                float at = sE[n0 + i][m];
                acc[i].x = fmaf(at, wv.x, acc[i].x);
                acc[i].y = fmaf(at, wv.y, acc[i].y);
                acc[i].z = fmaf(at, wv.z, acc[i].z);
                acc[i].w = fmaf(at, wv.w, acc[i].w);
            }
        }
#pragma unroll
        for (int i = 0; i < 4; i++) {
            int n_ = n0 + i;
            if (n_ < NN) {
                float4 wv = *(const float4*)&sWh[n_][o4];
                float4 v = make_float4(acc[i].x + 0.3f * wv.x,
                                       acc[i].y + 0.3f * wv.y,
                                       acc[i].z + 0.3f * wv.z,
                                       acc[i].w + 0.3f * wv.w);
                v.x = (v.x > 0.f) ? v.x : (__expf(v.x) - 1.f);
                v.y = (v.y > 0.f) ? v.y : (__expf(v.y) - 1.f);
                v.z = (v.z > 0.f) ? v.z : (__expf(v.z) - 1.f);
                v.w = (v.w > 0.f) ? v.w : (__expf(v.w) - 1.f);
                *(float4*)&out[(size_t)(b * NN + n_) * NT + h * OO + o4] = v;
            }
        }
    }
}

// ---------------------------------------------------------------------------
extern "C" void kernel_launch(void* const* d_in, const int* in_sizes, int n_in,
                              void* d_out, int out_size)
{
    const float* h_    = (const float*)d_in[0];  // (B, N, F)
    const float* probs = (const float*)d_in[1];  // (B, N*N)
    const float* u_    = (const float*)d_in[2];  // (B, N*N, 2)
    const float* W_    = (const float*)d_in[3];  // (H, F, O)
    const float* a_    = (const float*)d_in[4];  // (H, N, 2*O)
    float* out = (float*)d_out;

    prep_kernel<<<PREP_BLKS, 256>>>(probs, u_, W_);

    cudaFuncSetAttribute(gemm_f16, cudaFuncAttributeMaxDynamicSharedMemorySize,
                         SMEM_BYTES);
    gemm_f16<<<GRID_G, NTHREADS, SMEM_BYTES>>>(h_);

    dim3 agrid(BB, HH);
    attn_kernel<<<agrid, 256>>>(a_, out);
}